// round 16
// baseline (speedup 1.0000x reference)
#include <cuda_runtime.h>

typedef unsigned long long ull;

#define BB 16
#define HH 1024
#define WW 1024
#define R 4
#define KS 9
#define TX 64
#define TY 32
#define NT 256
#define IW 72              // TX + 2R input cols
#define IH 40              // TY + 2R input rows
#define SINW 74            // s_in padded stride (words): conflict-free, 8B rows
#define SHW 66             // s_h padded stride (words): conflict-free, 8B rows
#define P1_UNITS (IH * 8)  // 40 rows x 8 col-octets = 320

__device__ double g_acc;
__device__ unsigned int g_cnt;

__device__ __forceinline__ ull fma2(ull a, ull b, ull c) {
    ull d; asm("fma.rn.f32x2 %0, %1, %2, %3;" : "=l"(d) : "l"(a), "l"(b), "l"(c)); return d;
}
__device__ __forceinline__ ull mul2(ull a, ull b) {
    ull d; asm("mul.rn.f32x2 %0, %1, %2;" : "=l"(d) : "l"(a), "l"(b)); return d;
}
__device__ __forceinline__ ull pack2s(float x) {            // (x, x)
    ull d; asm("mov.b64 %0, {%1, %1};" : "=l"(d) : "f"(x)); return d;
}
__device__ __forceinline__ ull pack2f(float lo, float hi) { // (lo, hi)
    ull d; asm("mov.b64 %0, {%1, %2};" : "=l"(d) : "f"(lo), "f"(hi)); return d;
}
__device__ __forceinline__ float lo2(ull v) { return __int_as_float((int)(unsigned)v); }
__device__ __forceinline__ float hi2(ull v) { return __int_as_float((int)(v >> 32)); }

__global__ __launch_bounds__(NT, 3) void snake_fused_kernel(
    const float* __restrict__ pred,
    const float* __restrict__ snake,
    const float* __restrict__ fltr,
    float* __restrict__ out)
{
    __shared__ __align__(16) float s_in[IH][SINW];   // 40x74 (72 valid)
    __shared__ __align__(16) float s_hg[IH][SHW];    // g_x result, 40x64 valid
    __shared__ __align__(16) float s_hd[IH][SHW];    // dg_x result
    __shared__ float s_cg[KS], s_cd[KS];
    __shared__ float s_red[NT / 32];

    const int tid = threadIdx.x;
    const int bx = blockIdx.x;   // 16
    const int by = blockIdx.y;   // 32
    const int b  = blockIdx.z;   // 16

    // ---- recover separable taps: f_dy = outer(dg, g), sum(g)=1 ----
    if (tid < KS) {
        float s = 0.f;
        #pragma unroll
        for (int j = 0; j < KS; ++j) s += fltr[tid * KS + j];
        s_cd[tid] = s;                                  // dg[i]
    }
    __syncthreads();
    if (tid < KS) s_cg[tid] = fltr[tid] / s_cd[0];      // g[j]

    // ---- load input tile with halo ----
    const int x0 = bx * TX - R;
    const int y0 = by * TY - R;
    const size_t plane = (size_t)HH * WW;
    const float* pb = pred + (size_t)b * plane;
    for (int i = tid; i < IH * IW; i += NT) {
        int rx = i % IW, ry = i / IW;
        int gx = x0 + rx, gy = y0 + ry;
        float v = 0.f;
        if (gx >= 0 && gx < WW && gy >= 0 && gy < HH) v = pb[(size_t)gy * WW + gx];
        s_in[ry][rx] = v;
    }
    __syncthreads();

    const float* sb = snake + (size_t)b * plane;
    float lacc = 0.f;

    const int c  = tid & 63;        // pass-2 column (lane-contiguous)
    const int qd = tid >> 6;        // pass-2 row quarter
    const int y0r = qd * 8;

    for (int phase = 0; phase < 2; ++phase) {
        float* outg = out + 1 + (size_t)phase * ((size_t)BB * 2 * plane)
                            + ((size_t)b * 2) * plane;

        // ===== Pass 1: horizontal conv over all 40 rows, f32x2 on col pairs =====
        for (int u = tid; u < P1_UNITS; u += NT) {
            int r = u >> 3;
            int o = (u & 7) * 8;     // first output col of this octet

            ull t[8];
            #pragma unroll
            for (int k = 0; k < 8; ++k) {
                ull v = *(const ull*)&s_in[r][o + 2 * k];
                if (phase) v &= 0x7FFFFFFF7FFFFFFFull;     // |pred|
                t[k] = v;
            }
            // shifted pairs q[k] = (w[k], w[k+1]), k = 0..14
            ull q[15];
            #pragma unroll
            for (int m = 0; m < 7; ++m) {
                q[2 * m]     = t[m];
                q[2 * m + 1] = pack2f(hi2(t[m]), lo2(t[m + 1]));
            }
            q[14] = t[7];

            #pragma unroll
            for (int p = 0; p < 4; ++p) {
                ull ag = mul2(pack2s(s_cg[0]), q[2 * p]);
                #pragma unroll
                for (int j = 1; j < KS; ++j)
                    ag = fma2(pack2s(s_cg[j]), q[2 * p + j], ag);
                *(ull*)&s_hg[r][o + 2 * p] = ag;

                ull ad = mul2(pack2s(s_cd[0]), q[2 * p]);
                #pragma unroll
                for (int j = 1; j < KS; ++j)
                    if (j != 4)                               // dg[4] == 0
                        ad = fma2(pack2s(s_cd[j]), q[2 * p + j], ad);
                *(ull*)&s_hd[r][o + 2 * p] = ad;
            }
        }
        __syncthreads();

        // ===== Pass 2: vertical conv, lane = column, 8 rows/thread =====
        {
            float* p0 = outg + (size_t)(by * TY + y0r) * WW + (bx * TX + c);
            float* p1 = p0 + plane;

            // ---- channel 0: dy = dg_y over s_hg ----
            {
                float h[16];
                #pragma unroll
                for (int k = 0; k < 16; ++k) h[k] = s_hg[y0r + k][c];
                ull v[15];
                #pragma unroll
                for (int k = 0; k < 15; ++k) v[k] = pack2f(h[k], h[k + 1]);
                #pragma unroll
                for (int p = 0; p < 4; ++p) {
                    ull a = mul2(pack2s(10.0f * s_cd[0]), v[2 * p]);
                    #pragma unroll
                    for (int j = 1; j < KS; ++j)
                        if (j != 4)
                            a = fma2(pack2s(10.0f * s_cd[j]), v[2 * p + j], a);
                    p0[(size_t)(2 * p) * WW]     = lo2(a);
                    p0[(size_t)(2 * p + 1) * WW] = hi2(a);
                }
            }
            // ---- channel 1: dx = g_y over s_hd ----
            {
                float h[16];
                #pragma unroll
                for (int k = 0; k < 16; ++k) h[k] = s_hd[y0r + k][c];
                ull v[15];
                #pragma unroll
                for (int k = 0; k < 15; ++k) v[k] = pack2f(h[k], h[k + 1]);
                #pragma unroll
                for (int p = 0; p < 4; ++p) {
                    ull a = mul2(pack2s(10.0f * s_cg[0]), v[2 * p]);
                    #pragma unroll
                    for (int j = 1; j < KS; ++j)
                        a = fma2(pack2s(10.0f * s_cg[j]), v[2 * p + j], a);
                    p1[(size_t)(2 * p) * WW]     = lo2(a);
                    p1[(size_t)(2 * p + 1) * WW] = hi2(a);
                }
            }
        }

        // ---- loss (phase 0 only): lane-contiguous snake loads ----
        if (phase == 0) {
            const float* srow = sb + (size_t)(by * TY + y0r) * WW + (bx * TX + c);
            #pragma unroll
            for (int rr = 0; rr < 8; ++rr) {
                float p = s_in[y0r + rr + R][c + R];
                float s = srow[(size_t)rr * WW];
                float sdv = (s > 0.f) ? 15.0f : 2.0f * s;
                float w   = (s < 0.f) ? 2.5f : 1.0f;
                float d = p - sdv;
                lacc = fmaf(d * d, w, lacc);
            }
            __syncthreads();   // s_hg/s_hd reused by phase B pass 1
        }
    }

    // ===== loss reduction + fused finalize =====
    #pragma unroll
    for (int off = 16; off; off >>= 1)
        lacc += __shfl_down_sync(0xffffffffu, lacc, off);
    if ((tid & 31) == 0) s_red[tid >> 5] = lacc;
    __syncthreads();
    if (tid < NT / 32) {
        float v = s_red[tid];
        #pragma unroll
        for (int off = NT / 64; off; off >>= 1)
            v += __shfl_down_sync(0xffu, v, off);
        if (tid == 0) {
            atomicAdd(&g_acc, (double)v);
            __threadfence();
            unsigned nblk = gridDim.x * gridDim.y * gridDim.z;
            unsigned t = atomicAdd(&g_cnt, 1u);
            if (t == nblk - 1) {
                double total = atomicAdd(&g_acc, 0.0);
                out[0] = (float)(total * (1.0 / ((double)BB * HH * WW)));
                g_acc = 0.0;
                g_cnt = 0u;
            }
        }
    }
}

extern "C" void kernel_launch(void* const* d_in, const int* in_sizes, int n_in,
                              void* d_out, int out_size) {
    const float* pred  = (const float*)d_in[0];
    const float* snake = (const float*)d_in[1];
    const float* fltr  = (const float*)d_in[2];
    float* out = (float*)d_out;

    dim3 grid(WW / TX, HH / TY, BB);
    snake_fused_kernel<<<grid, NT>>>(pred, snake, fltr, out);
}

// round 17
// speedup vs baseline: 1.0006x; 1.0006x over previous
#include <cuda_runtime.h>

typedef unsigned long long ull;

#define BB 16
#define HH 1024
#define WW 1024
#define R 4
#define KS 9
#define TX 64
#define TY 32
#define NT 256
#define IW 72              // TX + 2R input cols
#define IH 40              // TY + 2R input rows
#define SINW 74            // s_in padded stride (words): conflict-free, 8B rows
#define SHW 66             // s_h padded stride (words): conflict-free, 8B rows
#define P1_UNITS (IH * 8)  // 40 rows x 8 col-octets = 320

__device__ double g_acc;
__device__ unsigned int g_cnt;

__device__ __forceinline__ ull fma2(ull a, ull b, ull c) {
    ull d; asm("fma.rn.f32x2 %0, %1, %2, %3;" : "=l"(d) : "l"(a), "l"(b), "l"(c)); return d;
}
__device__ __forceinline__ ull mul2(ull a, ull b) {
    ull d; asm("mul.rn.f32x2 %0, %1, %2;" : "=l"(d) : "l"(a), "l"(b)); return d;
}
__device__ __forceinline__ ull pack2s(float x) {            // (x, x)
    ull d; asm("mov.b64 %0, {%1, %1};" : "=l"(d) : "f"(x)); return d;
}
__device__ __forceinline__ ull pack2f(float lo, float hi) { // (lo, hi)
    ull d; asm("mov.b64 %0, {%1, %2};" : "=l"(d) : "f"(lo), "f"(hi)); return d;
}
__device__ __forceinline__ float lo2(ull v) { return __int_as_float((int)(unsigned)v); }
__device__ __forceinline__ float hi2(ull v) { return __int_as_float((int)(v >> 32)); }

__global__ __launch_bounds__(NT, 3) void snake_fused_kernel(
    const float* __restrict__ pred,
    const float* __restrict__ snake,
    const float* __restrict__ fltr,
    float* __restrict__ out)
{
    __shared__ __align__(16) float s_in[IH][SINW];   // 40x74 (72 valid)
    __shared__ __align__(16) float s_hg[IH][SHW];    // g_x result, 40x64 valid
    __shared__ __align__(16) float s_hd[IH][SHW];    // dg_x result
    __shared__ float s_cg[KS], s_cd[KS];
    __shared__ float s_red[NT / 32];

    const int tid = threadIdx.x;
    const int bx = blockIdx.x;   // 16
    const int by = blockIdx.y;   // 32
    const int b  = blockIdx.z;   // 16

    // ---- recover separable taps: f_dy = outer(dg, g), sum(g)=1 ----
    if (tid < KS) {
        float s = 0.f;
        #pragma unroll
        for (int j = 0; j < KS; ++j) s += fltr[tid * KS + j];
        s_cd[tid] = s;                                  // dg[i]
    }
    __syncthreads();
    if (tid < KS) s_cg[tid] = fltr[tid] / s_cd[0];      // g[j]

    // ---- load input tile with halo ----
    const int x0 = bx * TX - R;
    const int y0 = by * TY - R;
    const size_t plane = (size_t)HH * WW;
    const float* pb = pred + (size_t)b * plane;
    for (int i = tid; i < IH * IW; i += NT) {
        int rx = i % IW, ry = i / IW;
        int gx = x0 + rx, gy = y0 + ry;
        float v = 0.f;
        if (gx >= 0 && gx < WW && gy >= 0 && gy < HH) v = pb[(size_t)gy * WW + gx];
        s_in[ry][rx] = v;
    }
    __syncthreads();

    const float* sb = snake + (size_t)b * plane;
    float lacc = 0.f;

    const int c  = tid & 63;        // pass-2 column (lane-contiguous)
    const int qd = tid >> 6;        // pass-2 row quarter
    const int y0r = qd * 8;

    for (int phase = 0; phase < 2; ++phase) {
        float* outg = out + 1 + (size_t)phase * ((size_t)BB * 2 * plane)
                            + ((size_t)b * 2) * plane;

        // ===== Pass 1: horizontal conv over all 40 rows, f32x2 on col pairs =====
        for (int u = tid; u < P1_UNITS; u += NT) {
            int r = u >> 3;
            int o = (u & 7) * 8;     // first output col of this octet

            ull t[8];
            #pragma unroll
            for (int k = 0; k < 8; ++k) {
                ull v = *(const ull*)&s_in[r][o + 2 * k];
                if (phase) v &= 0x7FFFFFFF7FFFFFFFull;     // |pred|
                t[k] = v;
            }
            // shifted pairs q[k] = (w[k], w[k+1]), k = 0..14
            ull q[15];
            #pragma unroll
            for (int m = 0; m < 7; ++m) {
                q[2 * m]     = t[m];
                q[2 * m + 1] = pack2f(hi2(t[m]), lo2(t[m + 1]));
            }
            q[14] = t[7];

            #pragma unroll
            for (int p = 0; p < 4; ++p) {
                ull ag = mul2(pack2s(s_cg[0]), q[2 * p]);
                #pragma unroll
                for (int j = 1; j < KS; ++j)
                    ag = fma2(pack2s(s_cg[j]), q[2 * p + j], ag);
                *(ull*)&s_hg[r][o + 2 * p] = ag;

                ull ad = mul2(pack2s(s_cd[0]), q[2 * p]);
                #pragma unroll
                for (int j = 1; j < KS; ++j)
                    if (j != 4)                               // dg[4] == 0
                        ad = fma2(pack2s(s_cd[j]), q[2 * p + j], ad);
                *(ull*)&s_hd[r][o + 2 * p] = ad;
            }
        }
        __syncthreads();

        // ===== Pass 2: vertical conv, lane = column, 8 rows/thread =====
        {
            float* p0 = outg + (size_t)(by * TY + y0r) * WW + (bx * TX + c);
            float* p1 = p0 + plane;

            // ---- channel 0: dy = dg_y over s_hg ----
            {
                float h[16];
                #pragma unroll
                for (int k = 0; k < 16; ++k) h[k] = s_hg[y0r + k][c];
                ull v[15];
                #pragma unroll
                for (int k = 0; k < 15; ++k) v[k] = pack2f(h[k], h[k + 1]);
                #pragma unroll
                for (int p = 0; p < 4; ++p) {
                    ull a = mul2(pack2s(10.0f * s_cd[0]), v[2 * p]);
                    #pragma unroll
                    for (int j = 1; j < KS; ++j)
                        if (j != 4)
                            a = fma2(pack2s(10.0f * s_cd[j]), v[2 * p + j], a);
                    p0[(size_t)(2 * p) * WW]     = lo2(a);
                    p0[(size_t)(2 * p + 1) * WW] = hi2(a);
                }
            }
            // ---- channel 1: dx = g_y over s_hd ----
            {
                float h[16];
                #pragma unroll
                for (int k = 0; k < 16; ++k) h[k] = s_hd[y0r + k][c];
                ull v[15];
                #pragma unroll
                for (int k = 0; k < 15; ++k) v[k] = pack2f(h[k], h[k + 1]);
                #pragma unroll
                for (int p = 0; p < 4; ++p) {
                    ull a = mul2(pack2s(10.0f * s_cg[0]), v[2 * p]);
                    #pragma unroll
                    for (int j = 1; j < KS; ++j)
                        a = fma2(pack2s(10.0f * s_cg[j]), v[2 * p + j], a);
                    p1[(size_t)(2 * p) * WW]     = lo2(a);
                    p1[(size_t)(2 * p + 1) * WW] = hi2(a);
                }
            }
        }

        // ---- loss (phase 0 only): lane-contiguous snake loads ----
        if (phase == 0) {
            const float* srow = sb + (size_t)(by * TY + y0r) * WW + (bx * TX + c);
            #pragma unroll
            for (int rr = 0; rr < 8; ++rr) {
                float p = s_in[y0r + rr + R][c + R];
                float s = srow[(size_t)rr * WW];
                float sdv = (s > 0.f) ? 15.0f : 2.0f * s;
                float w   = (s < 0.f) ? 2.5f : 1.0f;
                float d = p - sdv;
                lacc = fmaf(d * d, w, lacc);
            }
            __syncthreads();   // s_hg/s_hd reused by phase B pass 1
        }
    }

    // ===== loss reduction + fused finalize =====
    #pragma unroll
    for (int off = 16; off; off >>= 1)
        lacc += __shfl_down_sync(0xffffffffu, lacc, off);
    if ((tid & 31) == 0) s_red[tid >> 5] = lacc;
    __syncthreads();
    if (tid < NT / 32) {
        float v = s_red[tid];
        #pragma unroll
        for (int off = NT / 64; off; off >>= 1)
            v += __shfl_down_sync(0xffu, v, off);
        if (tid == 0) {
            atomicAdd(&g_acc, (double)v);
            __threadfence();
            unsigned nblk = gridDim.x * gridDim.y * gridDim.z;
            unsigned t = atomicAdd(&g_cnt, 1u);
            if (t == nblk - 1) {
                double total = atomicAdd(&g_acc, 0.0);
                out[0] = (float)(total * (1.0 / ((double)BB * HH * WW)));
                g_acc = 0.0;
                g_cnt = 0u;
            }
        }
    }
}

extern "C" void kernel_launch(void* const* d_in, const int* in_sizes, int n_in,
                              void* d_out, int out_size) {
    const float* pred  = (const float*)d_in[0];
    const float* snake = (const float*)d_in[1];
    const float* fltr  = (const float*)d_in[2];
    float* out = (float*)d_out;

    dim3 grid(WW / TX, HH / TY, BB);
    snake_fused_kernel<<<grid, NT>>>(pred, snake, fltr, out);
}